// round 3
// baseline (speedup 1.0000x reference)
#include <cuda_runtime.h>
#include <cuda_bf16.h>

#define NMAX 100000
#define EMAX 1250000
#define DD 64

typedef unsigned long long u64;

__device__ __forceinline__ u64 ffma2(u64 a, u64 b, u64 c) {
    u64 d;
    asm("fma.rn.f32x2 %0, %1, %2, %3;" : "=l"(d) : "l"(a), "l"(b), "l"(c));
    return d;
}
__device__ __forceinline__ u64 pack2(float lo, float hi) {
    u64 d;
    asm("mov.b64 %0, {%1, %2};" : "=l"(d) : "r"(__float_as_uint(lo)), "r"(__float_as_uint(hi)));
    return d;
}
__device__ __forceinline__ float2 unpack2(u64 v) {
    unsigned lo, hi;
    asm("mov.b64 {%0, %1}, %2;" : "=r"(lo), "=r"(hi) : "l"(v));
    return make_float2(__uint_as_float(lo), __uint_as_float(hi));
}

// ---------------- scratch ----------------
__device__ int   g_degi[NMAX];
__device__ float g_dis[NMAX];
__device__ int   g_rowptr[NMAX + 1];
__device__ int   g_cursor[NMAX];
__device__ int   g_csr[EMAX];
__device__ int   g_blocksums[512];
__device__ float g_bufA[(size_t)NMAX * DD];
__device__ float g_bufB[(size_t)NMAX * DD];
__device__ float g_bufC[(size_t)NMAX * DD];

// ---------------- degree / norm ----------------
__global__ void deg_count_kernel(const int* __restrict__ dst, int E, int* __restrict__ degi) {
    int i = blockIdx.x * blockDim.x + threadIdx.x;
    if (i < E) atomicAdd(&degi[dst[i]], 1);
}
__global__ void dis_kernel(const int* __restrict__ degi, float* __restrict__ dis, int n) {
    int i = blockIdx.x * blockDim.x + threadIdx.x;
    if (i < n) dis[i] = rsqrtf((float)degi[i] + 1.0f);
}

// ---------------- exclusive scan (n <= 512*512) ----------------
__global__ void scan1_kernel(const int* __restrict__ cnt, int* __restrict__ out,
                             int* __restrict__ bsums, int n) {
    __shared__ int s[512];
    int i = blockIdx.x * 512 + threadIdx.x;
    int v = (i < n) ? cnt[i] : 0;
    s[threadIdx.x] = v;
    __syncthreads();
    for (int off = 1; off < 512; off <<= 1) {
        int t = (threadIdx.x >= off) ? s[threadIdx.x - off] : 0;
        __syncthreads();
        s[threadIdx.x] += t;
        __syncthreads();
    }
    if (i < n) out[i] = s[threadIdx.x] - v;
    if (threadIdx.x == 511) bsums[blockIdx.x] = s[511];
}
__global__ void scan2_kernel(int* __restrict__ bsums, int nb) {
    __shared__ int s[512];
    int v = (threadIdx.x < nb) ? bsums[threadIdx.x] : 0;
    s[threadIdx.x] = v;
    __syncthreads();
    for (int off = 1; off < 512; off <<= 1) {
        int t = (threadIdx.x >= off) ? s[threadIdx.x - off] : 0;
        __syncthreads();
        s[threadIdx.x] += t;
        __syncthreads();
    }
    if (threadIdx.x < nb) bsums[threadIdx.x] = s[threadIdx.x] - v;
}
__global__ void scan3_kernel(int* __restrict__ rowptr, const int* __restrict__ bsums,
                             int* __restrict__ cursor, int n, int E) {
    int i = blockIdx.x * 512 + threadIdx.x;
    if (i < n) {
        int v = rowptr[i] + bsums[blockIdx.x];
        rowptr[i] = v;
        cursor[i] = v;
    }
    if (i == n) rowptr[n] = E;
}
__global__ void fill_csr_kernel(const int* __restrict__ src, const int* __restrict__ dst,
                                int* __restrict__ cursor, int* __restrict__ csr, int E) {
    int i = blockIdx.x * blockDim.x + threadIdx.x;
    if (i < E) {
        int pos = atomicAdd(&cursor[dst[i]], 1);
        csr[pos] = src[i];
    }
}

// ---------------- gather (CSR), shfl-broadcast indices ----------------
// GCN=true : out = relu?(sum_e xw[s]*dis[s]*dis[d] + xw[d]*dis[d]^2 + bias)
// GCN=false: out = (sum_e h[s]) / max(deg,1)   (mean folded in)
template <bool GCN, bool RELU>
__global__ void gather_kernel(const int* __restrict__ rowptr, const int* __restrict__ csr,
                              const float* __restrict__ xw, const float* __restrict__ dis,
                              const float* __restrict__ bias, float* __restrict__ out, int n) {
    int node = blockIdx.x * 16 + (threadIdx.x >> 4);
    int q = threadIdx.x & 15;
    unsigned gmask = 0xFFFFu << (threadIdx.x & 16);
    bool valid = node < n;
    int beg = 0, end = 0;
    if (valid) { beg = rowptr[node]; end = rowptr[node + 1]; }
    float4 acc = make_float4(0.f, 0.f, 0.f, 0.f);
    const float4* xwv = (const float4*)xw;
    for (int e = beg; e < end; e += 16) {
        int cnt = min(16, end - e);
        int s_mine = (q < cnt) ? csr[e + q] : 0;
        float d_mine = GCN ? dis[s_mine] : 0.f;
        for (int j = 0; j < cnt; j++) {
            int s = __shfl_sync(gmask, s_mine, j, 16);
            float4 v = xwv[(size_t)s * 16 + q];
            if (GCN) {
                float w = __shfl_sync(gmask, d_mine, j, 16);
                acc.x = fmaf(v.x, w, acc.x); acc.y = fmaf(v.y, w, acc.y);
                acc.z = fmaf(v.z, w, acc.z); acc.w = fmaf(v.w, w, acc.w);
            } else {
                acc.x += v.x; acc.y += v.y; acc.z += v.z; acc.w += v.w;
            }
        }
    }
    if (!valid) return;
    if (GCN) {
        float dd = dis[node];
        float d2 = dd * dd;
        float4 xv = xwv[(size_t)node * 16 + q];
        float4 bb = ((const float4*)bias)[q];
        acc.x = fmaf(acc.x, dd, fmaf(xv.x, d2, bb.x));
        acc.y = fmaf(acc.y, dd, fmaf(xv.y, d2, bb.y));
        acc.z = fmaf(acc.z, dd, fmaf(xv.z, d2, bb.z));
        acc.w = fmaf(acc.w, dd, fmaf(xv.w, d2, bb.w));
        if (RELU) {
            acc.x = fmaxf(acc.x, 0.f); acc.y = fmaxf(acc.y, 0.f);
            acc.z = fmaxf(acc.z, 0.f); acc.w = fmaxf(acc.w, 0.f);
        }
    } else {
        float dinv = 1.0f / fmaxf((float)(end - beg), 1.0f);
        acc.x *= dinv; acc.y *= dinv; acc.z *= dinv; acc.w *= dinv;
    }
    ((float4*)out)[(size_t)node * 16 + q] = acc;
}

// ---------------- GEMM via FFMA2: out = act(X @ W [+ b]) ----------------
// dyn smem: Wp[64][32] u64 (16KB) + Xd[64][64] u64 dup (32KB) = 48KB+
template <bool RELU, bool BIAS>
__global__ void __launch_bounds__(256) gemm64_kernel(
    const float* __restrict__ X, const float* __restrict__ W,
    const float* __restrict__ bias, float* __restrict__ out, int n) {
    extern __shared__ char smraw[];
    u64* Wp = (u64*)smraw;               // Wp[k*32 + c2] = (W[k][2c2], W[k][2c2+1])
    u64* Xd = (u64*)(smraw + 16384);     // Xd[k*64 + r] = (x,x)
    int tid = threadIdx.x;
    int row0 = blockIdx.x * 64;

    {   // load W as pairs (natural layout: consecutive floats)
        const u64* Wv = (const u64*)W;
        for (int i = tid; i < 2048; i += 256) Wp[i] = Wv[i];
    }
    for (int j = tid; j < 1024; j += 256) {   // load+transpose+dup X tile
        int r = j >> 4, cg = j & 15;
        float4 v = (row0 + r < n) ? ((const float4*)X)[(size_t)(row0 + r) * 16 + cg]
                                  : make_float4(0.f, 0.f, 0.f, 0.f);
        int c = cg * 4;
        Xd[(c + 0) * 64 + r] = pack2(v.x, v.x);
        Xd[(c + 1) * 64 + r] = pack2(v.y, v.y);
        Xd[(c + 2) * 64 + r] = pack2(v.z, v.z);
        Xd[(c + 3) * 64 + r] = pack2(v.w, v.w);
    }
    __syncthreads();

    int rq = (tid >> 4) * 4;        // 4 rows
    int c2 = (tid & 15) * 2;        // 2 col-pairs -> cols 4*(tid&15)..+3
    u64 acc[4][2];
#pragma unroll
    for (int i = 0; i < 4; i++) { acc[i][0] = 0ull; acc[i][1] = 0ull; }

#pragma unroll 4
    for (int k = 0; k < 64; k++) {
        u64 w0 = Wp[k * 32 + c2];
        u64 w1 = Wp[k * 32 + c2 + 1];
        const u64* xr = &Xd[k * 64 + rq];
        u64 x0 = xr[0], x1 = xr[1], x2 = xr[2], x3 = xr[3];
        acc[0][0] = ffma2(x0, w0, acc[0][0]); acc[0][1] = ffma2(x0, w1, acc[0][1]);
        acc[1][0] = ffma2(x1, w0, acc[1][0]); acc[1][1] = ffma2(x1, w1, acc[1][1]);
        acc[2][0] = ffma2(x2, w0, acc[2][0]); acc[2][1] = ffma2(x2, w1, acc[2][1]);
        acc[3][0] = ffma2(x3, w0, acc[3][0]); acc[3][1] = ffma2(x3, w1, acc[3][1]);
    }

    int cg = tid & 15;
    float4 bb = BIAS ? ((const float4*)bias)[cg] : make_float4(0.f, 0.f, 0.f, 0.f);
#pragma unroll
    for (int i = 0; i < 4; i++) {
        int row = row0 + rq + i;
        if (row < n) {
            float2 p0 = unpack2(acc[i][0]);
            float2 p1 = unpack2(acc[i][1]);
            float4 o = make_float4(p0.x + bb.x, p0.y + bb.y, p1.x + bb.z, p1.y + bb.w);
            if (RELU) {
                o.x = fmaxf(o.x, 0.f); o.y = fmaxf(o.y, 0.f);
                o.z = fmaxf(o.z, 0.f); o.w = fmaxf(o.w, 0.f);
            }
            ((float4*)out)[(size_t)row * 16 + cg] = o;
        }
    }
}

// ---------------- SAGE combine: out = act(M @ Wl + bl + H @ Wr + H) ----------------
// M = mean (already divided in gather). dyn smem: Wl 16K + Wr 16K + Md 32K + Hd 32K = 96KB
template <bool RELU>
__global__ void __launch_bounds__(256) sage64_kernel(
    const float* __restrict__ M, const float* __restrict__ H,
    const float* __restrict__ Wl, const float* __restrict__ bl,
    const float* __restrict__ Wr, float* __restrict__ out, int n) {
    extern __shared__ char smraw[];
    u64* Wlp = (u64*)smraw;
    u64* Wrp = (u64*)(smraw + 16384);
    u64* Md  = (u64*)(smraw + 32768);
    u64* Hd  = (u64*)(smraw + 65536);
    int tid = threadIdx.x;
    int row0 = blockIdx.x * 64;

    {
        const u64* a = (const u64*)Wl;
        const u64* b = (const u64*)Wr;
        for (int i = tid; i < 2048; i += 256) { Wlp[i] = a[i]; Wrp[i] = b[i]; }
    }
    for (int j = tid; j < 1024; j += 256) {
        int r = j >> 4, cg = j & 15;
        float4 m = make_float4(0.f, 0.f, 0.f, 0.f), h = m;
        if (row0 + r < n) {
            m = ((const float4*)M)[(size_t)(row0 + r) * 16 + cg];
            h = ((const float4*)H)[(size_t)(row0 + r) * 16 + cg];
        }
        int c = cg * 4;
        Md[(c + 0) * 64 + r] = pack2(m.x, m.x);
        Md[(c + 1) * 64 + r] = pack2(m.y, m.y);
        Md[(c + 2) * 64 + r] = pack2(m.z, m.z);
        Md[(c + 3) * 64 + r] = pack2(m.w, m.w);
        Hd[(c + 0) * 64 + r] = pack2(h.x, h.x);
        Hd[(c + 1) * 64 + r] = pack2(h.y, h.y);
        Hd[(c + 2) * 64 + r] = pack2(h.z, h.z);
        Hd[(c + 3) * 64 + r] = pack2(h.w, h.w);
    }
    __syncthreads();

    int rq = (tid >> 4) * 4;
    int c2 = (tid & 15) * 2;
    u64 acc[4][2];
#pragma unroll
    for (int i = 0; i < 4; i++) { acc[i][0] = 0ull; acc[i][1] = 0ull; }

#pragma unroll 2
    for (int k = 0; k < 64; k++) {
        u64 wl0 = Wlp[k * 32 + c2], wl1 = Wlp[k * 32 + c2 + 1];
        u64 wr0 = Wrp[k * 32 + c2], wr1 = Wrp[k * 32 + c2 + 1];
        const u64* mr = &Md[k * 64 + rq];
        const u64* hr = &Hd[k * 64 + rq];
#pragma unroll
        for (int i = 0; i < 4; i++) {
            u64 m = mr[i], h = hr[i];
            acc[i][0] = ffma2(m, wl0, ffma2(h, wr0, acc[i][0]));
            acc[i][1] = ffma2(m, wl1, ffma2(h, wr1, acc[i][1]));
        }
    }

    int cg = tid & 15;
    float4 bb = ((const float4*)bl)[cg];
    int c = cg * 4;
#pragma unroll
    for (int i = 0; i < 4; i++) {
        int row = row0 + rq + i;
        if (row < n) {
            float2 p0 = unpack2(acc[i][0]);
            float2 p1 = unpack2(acc[i][1]);
            // residual H (lo half of dup)
            float h0 = unpack2(Hd[(c + 0) * 64 + rq + i]).x;
            float h1 = unpack2(Hd[(c + 1) * 64 + rq + i]).x;
            float h2 = unpack2(Hd[(c + 2) * 64 + rq + i]).x;
            float h3 = unpack2(Hd[(c + 3) * 64 + rq + i]).x;
            float4 o = make_float4(p0.x + bb.x + h0, p0.y + bb.y + h1,
                                   p1.x + bb.z + h2, p1.y + bb.w + h3);
            if (RELU) {
                o.x = fmaxf(o.x, 0.f); o.y = fmaxf(o.y, 0.f);
                o.z = fmaxf(o.z, 0.f); o.w = fmaxf(o.w, 0.f);
            }
            ((float4*)out)[(size_t)row * 16 + cg] = o;
        }
    }
}

// ---------------- launch ----------------
extern "C" void kernel_launch(void* const* d_in, const int* in_sizes, int n_in,
                              void* d_out, int out_size) {
    const float* x      = (const float*)d_in[0];
    const int*   ei     = (const int*)d_in[1];
    const float* gcn1_w = (const float*)d_in[2];
    const float* gcn1_b = (const float*)d_in[3];
    const float* s1lw   = (const float*)d_in[4];
    const float* s1lb   = (const float*)d_in[5];
    const float* s1rw   = (const float*)d_in[6];
    const float* s2lw   = (const float*)d_in[7];
    const float* s2lb   = (const float*)d_in[8];
    const float* s2rw   = (const float*)d_in[9];
    const float* linw   = (const float*)d_in[10];
    const float* linb   = (const float*)d_in[11];
    const float* gcn2_w = (const float*)d_in[12];
    const float* gcn2_b = (const float*)d_in[13];

    int n = in_sizes[0] / 64;
    int E = in_sizes[1] / 2;
    const int* src = ei;
    const int* dst = ei + E;

    int *degi, *rowptr, *cursor, *csr, *bsums;
    float *dis, *A, *B, *C;
    cudaGetSymbolAddress((void**)&degi, g_degi);
    cudaGetSymbolAddress((void**)&dis, g_dis);
    cudaGetSymbolAddress((void**)&rowptr, g_rowptr);
    cudaGetSymbolAddress((void**)&cursor, g_cursor);
    cudaGetSymbolAddress((void**)&csr, g_csr);
    cudaGetSymbolAddress((void**)&bsums, g_blocksums);
    cudaGetSymbolAddress((void**)&A, g_bufA);
    cudaGetSymbolAddress((void**)&B, g_bufB);
    cudaGetSymbolAddress((void**)&C, g_bufC);

    const int GEMM_SMEM = 49152;
    const int SAGE_SMEM = 98304;
    cudaFuncSetAttribute(gemm64_kernel<false, false>, cudaFuncAttributeMaxDynamicSharedMemorySize, GEMM_SMEM);
    cudaFuncSetAttribute(gemm64_kernel<true, true>,   cudaFuncAttributeMaxDynamicSharedMemorySize, GEMM_SMEM);
    cudaFuncSetAttribute(sage64_kernel<true>,  cudaFuncAttributeMaxDynamicSharedMemorySize, SAGE_SMEM);
    cudaFuncSetAttribute(sage64_kernel<false>, cudaFuncAttributeMaxDynamicSharedMemorySize, SAGE_SMEM);

    const int GEMM_GRID = (n + 63) / 64;
    const int GATH_GRID = (n + 15) / 16;
    const int NB = (n + 511) / 512;

    // degrees + CSR build
    cudaMemsetAsync(degi, 0, n * sizeof(int));
    deg_count_kernel<<<(E + 255) / 256, 256>>>(dst, E, degi);
    dis_kernel<<<(n + 255) / 256, 256>>>(degi, dis, n);
    scan1_kernel<<<NB, 512>>>(degi, rowptr, bsums, n);
    scan2_kernel<<<1, 512>>>(bsums, NB);
    scan3_kernel<<<(n + 512) / 512, 512>>>(rowptr, bsums, cursor, n, E);
    fill_csr_kernel<<<(E + 255) / 256, 256>>>(src, dst, cursor, csr, E);

    // ---- layer 0: GCN1 + relu ----
    gemm64_kernel<false, false><<<GEMM_GRID, 256, GEMM_SMEM>>>(x, gcn1_w, nullptr, A, n);
    gather_kernel<true, true><<<GATH_GRID, 256>>>(rowptr, csr, A, dis, gcn1_b, C, n);

    // ---- layer 1: SAGE1 + residual + relu ----
    gather_kernel<false, false><<<GATH_GRID, 256>>>(rowptr, csr, C, dis, nullptr, B, n);  // mean
    sage64_kernel<true><<<GEMM_GRID, 256, SAGE_SMEM>>>(B, C, s1lw, s1lb, s1rw, A, n);

    // ---- layer 2: SAGE2 + residual ----
    gather_kernel<false, false><<<GATH_GRID, 256>>>(rowptr, csr, A, dis, nullptr, B, n);  // mean
    sage64_kernel<false><<<GEMM_GRID, 256, SAGE_SMEM>>>(B, A, s2lw, s2lb, s2rw, C, n);

    // ---- lin + relu ----
    gemm64_kernel<true, true><<<GEMM_GRID, 256, GEMM_SMEM>>>(C, linw, linb, A, n);

    // ---- layer 3: GCN2 ----
    gemm64_kernel<false, false><<<GEMM_GRID, 256, GEMM_SMEM>>>(A, gcn2_w, nullptr, C, n);
    gather_kernel<true, false><<<GATH_GRID, 256>>>(rowptr, csr, C, dis, gcn2_b, (float*)d_out, n);
}